// round 10
// baseline (speedup 1.0000x reference)
#include <cuda_runtime.h>
#include <cuda_bf16.h>

#define HH 2048
#define WW 2048

// Cosine matrix C[f][p] = cos((2p+1)*f*pi/16), hard-coded so the fully
// unrolled IDCT passes compile to FFMA-with-immediate (no LDS in the passes).
__device__ constexpr float CM[8][8] = {
  { 1.0f,         1.0f,         1.0f,         1.0f,         1.0f,         1.0f,         1.0f,         1.0f        },
  { 0.98078528f,  0.83146961f,  0.55557023f,  0.19509032f, -0.19509032f, -0.55557023f, -0.83146961f, -0.98078528f },
  { 0.92387953f,  0.38268343f, -0.38268343f, -0.92387953f, -0.92387953f, -0.38268343f,  0.38268343f,  0.92387953f },
  { 0.83146961f, -0.19509032f, -0.98078528f, -0.55557023f,  0.55557023f,  0.98078528f,  0.19509032f, -0.83146961f },
  { 0.70710678f, -0.70710678f, -0.70710678f,  0.70710678f,  0.70710678f, -0.70710678f, -0.70710678f,  0.70710678f },
  { 0.55557023f, -0.98078528f,  0.19509032f,  0.83146961f, -0.83146961f, -0.19509032f,  0.98078528f, -0.55557023f },
  { 0.38268343f, -0.92387953f,  0.92387953f, -0.38268343f, -0.38268343f,  0.92387953f, -0.92387953f,  0.38268343f },
  { 0.19509032f, -0.55557023f,  0.83146961f, -0.98078528f,  0.98078528f, -0.83146961f,  0.55557023f, -0.19509032f },
};

// One CTA = TWO adjacent 32x32 RGB tiles, software-pipelined:
//   stage sD | pass1(A) + issue LDG(B) | pass2(A) | epilogue(A) + pass1(B)
//   | pass2(B) | epilogue(B)
// Tile-B's global loads are issued ~2 barriers before first use, hiding DRAM
// latency behind tile-A's compute/stores. smem buffers sT/sP are reused A->B
// (disjoint phases). Planar pixel buffers: Y stride 32, chroma stride 18.
__global__ __launch_bounds__(256) void jpeg_decode_kernel(
    const float* __restrict__ ycoef, const float* __restrict__ cbcoef,
    const float* __restrict__ crcoef,
    const float* __restrict__ y_table, const float* __restrict__ c_table,
    const float* __restrict__ alpha, const float* __restrict__ shift,
    const float* __restrict__ matrix, const int* __restrict__ factor_i,
    float* __restrict__ out)
{
    __shared__ float sD[128];       // dequant scale: [0:64) Y, [64:128) chroma
    __shared__ float sM[9];         // matrix / 255  (sM[c*3+d])
    __shared__ float sK[3];         // folded constants per output channel
    __shared__ float sT[1728];      // transpose buffer, 24 * 72 (reused A/B)
    __shared__ float sPY[32 * 32];  // planar Y (raw idct)      (reused A/B)
    __shared__ float sPCb[16 * 18];
    __shared__ float sPCr[16 * 18];

    const int tid = threadIdx.x;
    const unsigned tx = blockIdx.x, ty = blockIdx.y, bz = blockIdx.z;
    const unsigned Wb8 = WW / 8, Wb16 = WW / 16;
    const unsigned nY = (HH / 8) * (WW / 8);
    const unsigned nC = (HH / 16) * (WW / 16);

    int fbits = factor_i[0];
    float fac = (fbits > 0 && fbits < (1 << 23)) ? (float)fbits
                                                 : __int_as_float(fbits);

    if (tid < 128) {
        const float* tab = (tid < 64) ? y_table : c_table;
        int o = tid & 63;
        sD[tid] = tab[o] * alpha[o] * fac * 0.25f;
    } else if (tid < 137) {
        sM[tid - 128] = matrix[tid - 128] * (1.0f / 255.0f);
    } else if (tid < 140) {
        int d = tid - 137;
        float k = 0.0f;
#pragma unroll
        for (int c = 0; c < 3; c++)
            k = fmaf(128.0f + shift[c], matrix[c * 3 + d], k);
        sK[d] = k * (1.0f / 255.0f);
    }

    const int q = tid >> 3;
    const int x = tid & 7;

    // ---- compute coefficient addresses for both tiles; issue tile-A loads ----
    const float4* gA = nullptr;
    const float4* gB = nullptr;
    int dsel = 0;
    if (tid < 192) {
        const float* src;
        unsigned n;
        unsigned tx2 = tx * 2;               // tile A x-index
        if (q < 16) {                        // Y blocks: 4x4
            int i = q >> 2, j = q & 3;
            n = bz * nY + (ty * 4 + i) * Wb8 + (tx2 * 4 + j);
            src = ycoef;
        } else if (q < 20) {                 // Cb blocks: 2x2
            int i = (q - 16) >> 1, j = q & 1;
            n = bz * nC + (ty * 2 + i) * Wb16 + (tx2 * 2 + j);
            src = cbcoef; dsel = 64;
        } else {                             // Cr blocks: 2x2
            int i = (q - 20) >> 1, j = q & 1;
            n = bz * nC + (ty * 2 + i) * Wb16 + (tx2 * 2 + j);
            src = crcoef; dsel = 64;
        }
        unsigned nB = n + (q < 16 ? 4u : 2u);   // tile B is +4 Y-blocks / +2 chroma
        gA = (const float4*)(src + (size_t)n * 64 + x * 8);
        gB = (const float4*)(src + (size_t)nB * 64 + x * 8);
    }
    float4 ra, rb;
    if (tid < 192) { ra = __ldcs(&gA[0]); rb = __ldcs(&gA[1]); }
    __syncthreads();   // sD/sM/sK ready

    // ---- scale row (reused for both tiles) ----
    float4 da, db4;
    if (tid < 192) {
        const int db = dsel + x * 8;
        da = *(const float4*)&sD[db];
        db4 = *(const float4*)&sD[db + 4];
    }

    float4 ra2, rb2;
    if (tid < 192) {
        // dequant A
        float a0 = ra.x * da.x, a1 = ra.y * da.y, a2 = ra.z * da.z, a3 = ra.w * da.w;
        float a4 = rb.x * db4.x, a5 = rb.y * db4.y, a6 = rb.z * db4.z, a7 = rb.w * db4.w;

        // issue tile-B loads now (ra/rb registers dead) — hidden behind A compute
        ra2 = __ldcs(&gB[0]); rb2 = __ldcs(&gB[1]);

        // pass 1 A
        float* d = &sT[q * 72 + x * 9];
#pragma unroll
        for (int v = 0; v < 8; v++) {
            float acc = a0 * CM[0][v];
            acc = fmaf(a1, CM[1][v], acc);
            acc = fmaf(a2, CM[2][v], acc);
            acc = fmaf(a3, CM[3][v], acc);
            acc = fmaf(a4, CM[4][v], acc);
            acc = fmaf(a5, CM[5][v], acc);
            acc = fmaf(a6, CM[6][v], acc);
            acc = fmaf(a7, CM[7][v], acc);
            d[v] = acc;
        }
    }
    __syncthreads();

    // ---- pass 2 A ----
    if (tid < 192) {
        const int v = x;
        float c0 = sT[q * 72 + 0 * 9 + v];
        float c1 = sT[q * 72 + 1 * 9 + v];
        float c2 = sT[q * 72 + 2 * 9 + v];
        float c3 = sT[q * 72 + 3 * 9 + v];
        float c4 = sT[q * 72 + 4 * 9 + v];
        float c5 = sT[q * 72 + 5 * 9 + v];
        float c6 = sT[q * 72 + 6 * 9 + v];
        float c7 = sT[q * 72 + 7 * 9 + v];

        float* dst; int stride;
        if (q < 16) { dst = &sPY[((q >> 2) * 8) * 32 + (q & 3) * 8 + v]; stride = 32; }
        else if (q < 20) { int b = q - 16; dst = &sPCb[((b >> 1) * 8) * 18 + (b & 1) * 8 + v]; stride = 18; }
        else { int b = q - 20; dst = &sPCr[((b >> 1) * 8) * 18 + (b & 1) * 8 + v]; stride = 18; }

#pragma unroll
        for (int u = 0; u < 8; u++) {
            float acc = c0 * CM[0][u];
            acc = fmaf(c1, CM[1][u], acc);
            acc = fmaf(c2, CM[2][u], acc);
            acc = fmaf(c3, CM[3][u], acc);
            acc = fmaf(c4, CM[4][u], acc);
            acc = fmaf(c5, CM[5][u], acc);
            acc = fmaf(c6, CM[6][u], acc);
            acc = fmaf(c7, CM[7][u], acc);
            dst[u * stride] = acc;
        }
    }
    __syncthreads();

    // epilogue constants
    const float M0 = sM[0], M1 = sM[1], M2 = sM[2];
    const float M3 = sM[3], M4 = sM[4], M5 = sM[5];
    const float M6 = sM[6], M7 = sM[7], M8 = sM[8];
    const float K0 = sK[0], K1 = sK[1], K2 = sK[2];
    const int py = tid >> 3;
    const int px0 = (tid & 7) * 4;
    const int cy = py >> 1, cxb = px0 >> 1;
    const unsigned HW = HH * WW;
    const unsigned base = bz * 3u * HW;
    const unsigned gy = ty * 32 + py;

    // ---- epilogue A (stores) + pass1 B (writes sT) in the same phase ----
    {
        float2 cbv = *(const float2*)&sPCb[cy * 18 + cxb];
        float2 crv = *(const float2*)&sPCr[cy * 18 + cxb];
        float4 yv = *(const float4*)&sPY[py * 32 + px0];

        float bR0 = fmaf(cbv.x, M3, fmaf(crv.x, M6, K0));
        float bG0 = fmaf(cbv.x, M4, fmaf(crv.x, M7, K1));
        float bB0 = fmaf(cbv.x, M5, fmaf(crv.x, M8, K2));
        float bR1 = fmaf(cbv.y, M3, fmaf(crv.y, M6, K0));
        float bG1 = fmaf(cbv.y, M4, fmaf(crv.y, M7, K1));
        float bB1 = fmaf(cbv.y, M5, fmaf(crv.y, M8, K2));

        float4 oR, oG, oB;
        oR.x = __saturatef(fmaf(yv.x, M0, bR0));
        oG.x = __saturatef(fmaf(yv.x, M1, bG0));
        oB.x = __saturatef(fmaf(yv.x, M2, bB0));
        oR.y = __saturatef(fmaf(yv.y, M0, bR0));
        oG.y = __saturatef(fmaf(yv.y, M1, bG0));
        oB.y = __saturatef(fmaf(yv.y, M2, bB0));
        oR.z = __saturatef(fmaf(yv.z, M0, bR1));
        oG.z = __saturatef(fmaf(yv.z, M1, bG1));
        oB.z = __saturatef(fmaf(yv.z, M2, bB1));
        oR.w = __saturatef(fmaf(yv.w, M0, bR1));
        oG.w = __saturatef(fmaf(yv.w, M1, bG1));
        oB.w = __saturatef(fmaf(yv.w, M2, bB1));

        const unsigned gx = (tx * 2) * 32 + px0;
        const unsigned off = gy * WW + gx;
        __stcs((float4*)(out + base + off), oR);
        __stcs((float4*)(out + base + HW + off), oG);
        __stcs((float4*)(out + base + 2u * HW + off), oB);
    }
    // NOTE: no barrier here — sT (written below) vs sP (read above) disjoint,
    // and every thread finished its pass2-A sP writes before the last barrier.
    if (tid < 192) {
        // dequant B + pass 1 B
        float a0 = ra2.x * da.x, a1 = ra2.y * da.y, a2 = ra2.z * da.z, a3 = ra2.w * da.w;
        float a4 = rb2.x * db4.x, a5 = rb2.y * db4.y, a6 = rb2.z * db4.z, a7 = rb2.w * db4.w;
        float* d = &sT[q * 72 + x * 9];
#pragma unroll
        for (int v = 0; v < 8; v++) {
            float acc = a0 * CM[0][v];
            acc = fmaf(a1, CM[1][v], acc);
            acc = fmaf(a2, CM[2][v], acc);
            acc = fmaf(a3, CM[3][v], acc);
            acc = fmaf(a4, CM[4][v], acc);
            acc = fmaf(a5, CM[5][v], acc);
            acc = fmaf(a6, CM[6][v], acc);
            acc = fmaf(a7, CM[7][v], acc);
            d[v] = acc;
        }
    }
    __syncthreads();

    // ---- pass 2 B ----
    if (tid < 192) {
        const int v = x;
        float c0 = sT[q * 72 + 0 * 9 + v];
        float c1 = sT[q * 72 + 1 * 9 + v];
        float c2 = sT[q * 72 + 2 * 9 + v];
        float c3 = sT[q * 72 + 3 * 9 + v];
        float c4 = sT[q * 72 + 4 * 9 + v];
        float c5 = sT[q * 72 + 5 * 9 + v];
        float c6 = sT[q * 72 + 6 * 9 + v];
        float c7 = sT[q * 72 + 7 * 9 + v];

        float* dst; int stride;
        if (q < 16) { dst = &sPY[((q >> 2) * 8) * 32 + (q & 3) * 8 + v]; stride = 32; }
        else if (q < 20) { int b = q - 16; dst = &sPCb[((b >> 1) * 8) * 18 + (b & 1) * 8 + v]; stride = 18; }
        else { int b = q - 20; dst = &sPCr[((b >> 1) * 8) * 18 + (b & 1) * 8 + v]; stride = 18; }

#pragma unroll
        for (int u = 0; u < 8; u++) {
            float acc = c0 * CM[0][u];
            acc = fmaf(c1, CM[1][u], acc);
            acc = fmaf(c2, CM[2][u], acc);
            acc = fmaf(c3, CM[3][u], acc);
            acc = fmaf(c4, CM[4][u], acc);
            acc = fmaf(c5, CM[5][u], acc);
            acc = fmaf(c6, CM[6][u], acc);
            acc = fmaf(c7, CM[7][u], acc);
            dst[u * stride] = acc;
        }
    }
    __syncthreads();

    // ---- epilogue B ----
    {
        float2 cbv = *(const float2*)&sPCb[cy * 18 + cxb];
        float2 crv = *(const float2*)&sPCr[cy * 18 + cxb];
        float4 yv = *(const float4*)&sPY[py * 32 + px0];

        float bR0 = fmaf(cbv.x, M3, fmaf(crv.x, M6, K0));
        float bG0 = fmaf(cbv.x, M4, fmaf(crv.x, M7, K1));
        float bB0 = fmaf(cbv.x, M5, fmaf(crv.x, M8, K2));
        float bR1 = fmaf(cbv.y, M3, fmaf(crv.y, M6, K0));
        float bG1 = fmaf(cbv.y, M4, fmaf(crv.y, M7, K1));
        float bB1 = fmaf(cbv.y, M5, fmaf(crv.y, M8, K2));

        float4 oR, oG, oB;
        oR.x = __saturatef(fmaf(yv.x, M0, bR0));
        oG.x = __saturatef(fmaf(yv.x, M1, bG0));
        oB.x = __saturatef(fmaf(yv.x, M2, bB0));
        oR.y = __saturatef(fmaf(yv.y, M0, bR0));
        oG.y = __saturatef(fmaf(yv.y, M1, bG0));
        oB.y = __saturatef(fmaf(yv.y, M2, bB0));
        oR.z = __saturatef(fmaf(yv.z, M0, bR1));
        oG.z = __saturatef(fmaf(yv.z, M1, bG1));
        oB.z = __saturatef(fmaf(yv.z, M2, bB1));
        oR.w = __saturatef(fmaf(yv.w, M0, bR1));
        oG.w = __saturatef(fmaf(yv.w, M1, bG1));
        oB.w = __saturatef(fmaf(yv.w, M2, bB1));

        const unsigned gx = (tx * 2 + 1) * 32 + px0;
        const unsigned off = gy * WW + gx;
        __stcs((float4*)(out + base + off), oR);
        __stcs((float4*)(out + base + HW + off), oG);
        __stcs((float4*)(out + base + 2u * HW + off), oB);
    }
}

extern "C" void kernel_launch(void* const* d_in, const int* in_sizes, int n_in,
                              void* d_out, int out_size) {
    const float* y      = (const float*)d_in[0];
    const float* cb     = (const float*)d_in[1];
    const float* cr     = (const float*)d_in[2];
    const float* ytab   = (const float*)d_in[3];
    const float* ctab   = (const float*)d_in[4];
    const float* alpha  = (const float*)d_in[5];
    // d_in[6] = dct_tensor (unused; cosine basis hard-coded)
    const float* shift  = (const float*)d_in[7];
    const float* matrix = (const float*)d_in[8];
    const int* factor   = (const int*)d_in[11];

    int B = in_sizes[0] / (2048 * 2048);
    if (B < 1) B = 1;

    dim3 grid(WW / 64, HH / 32, B);
    jpeg_decode_kernel<<<grid, 256>>>(y, cb, cr, ytab, ctab, alpha, shift,
                                      matrix, factor, (float*)d_out);
}

// round 15
// speedup vs baseline: 1.0597x; 1.0597x over previous
#include <cuda_runtime.h>
#include <cuda_bf16.h>

#define HH 2048
#define WW 2048

__device__ constexpr float CM[8][8] = {
  { 1.0f,         1.0f,         1.0f,         1.0f,         1.0f,         1.0f,         1.0f,         1.0f        },
  { 0.98078528f,  0.83146961f,  0.55557023f,  0.19509032f, -0.19509032f, -0.55557023f, -0.83146961f, -0.98078528f },
  { 0.92387953f,  0.38268343f, -0.38268343f, -0.92387953f, -0.92387953f, -0.38268343f,  0.38268343f,  0.92387953f },
  { 0.83146961f, -0.19509032f, -0.98078528f, -0.55557023f,  0.55557023f,  0.98078528f,  0.19509032f, -0.83146961f },
  { 0.70710678f, -0.70710678f, -0.70710678f,  0.70710678f,  0.70710678f, -0.70710678f, -0.70710678f,  0.70710678f },
  { 0.55557023f, -0.98078528f,  0.19509032f,  0.83146961f, -0.83146961f, -0.19509032f,  0.98078528f, -0.55557023f },
  { 0.38268343f, -0.92387953f,  0.92387953f, -0.38268343f, -0.38268343f,  0.92387953f, -0.92387953f,  0.38268343f },
  { 0.19509032f, -0.55557023f,  0.83146961f, -0.98078528f,  0.98078528f, -0.83146961f,  0.55557023f, -0.19509032f },
};

// One CTA = TWO adjacent 32x32 RGB tiles.
// Tile A: classic LDG->regs path (identical to the 104.5us R7 kernel).
// Tile B: prefetched at kernel start via cp.async (LDGSTS) into smem bufB —
// zero register cost, so occupancy stays at the R7 level while B's DRAM
// latency is hidden behind A's entire compute.
// bufB layout: 96-word slot per block, word = q*96 + 12*x (max 92 < 96).
// 12-word stride -> 16B read banks {0,12,24,4,16,28,8,20}: conflict-free.
__global__ __launch_bounds__(256) void jpeg_decode_kernel(
    const float* __restrict__ ycoef, const float* __restrict__ cbcoef,
    const float* __restrict__ crcoef,
    const float* __restrict__ y_table, const float* __restrict__ c_table,
    const float* __restrict__ alpha, const float* __restrict__ shift,
    const float* __restrict__ matrix, const int* __restrict__ factor_i,
    float* __restrict__ out)
{
    __shared__ float sD[128];
    __shared__ float sM[9];
    __shared__ float sK[3];
    __shared__ float sT[1728];                    // 24 * 72 (reused A/B)
    __shared__ float sPY[32 * 32];                // (reused A/B)
    __shared__ float sPCb[16 * 18];
    __shared__ float sPCr[16 * 18];
    __shared__ __align__(16) float bufB[24 * 96]; // tile-B coeff staging

    const int tid = threadIdx.x;
    const unsigned tx = blockIdx.x, ty = blockIdx.y, bz = blockIdx.z;
    const unsigned Wb8 = WW / 8, Wb16 = WW / 16;
    const unsigned nY = (HH / 8) * (WW / 8);
    const unsigned nC = (HH / 16) * (WW / 16);

    int fbits = factor_i[0];
    float fac = (fbits > 0 && fbits < (1 << 23)) ? (float)fbits
                                                 : __int_as_float(fbits);

    const int q = tid >> 3;
    const int x = tid & 7;

    // ---- issue tile-A LDG (regs) and tile-B cp.async (smem) first ----
    float4 ra, rb;
    int dsel = 0;
    if (tid < 192) {
        const float* src;
        unsigned n;
        unsigned tx2 = tx * 2;
        if (q < 16) {
            int i = q >> 2, j = q & 3;
            n = bz * nY + (ty * 4 + i) * Wb8 + (tx2 * 4 + j);
            src = ycoef;
        } else if (q < 20) {
            int i = (q - 16) >> 1, j = q & 1;
            n = bz * nC + (ty * 2 + i) * Wb16 + (tx2 * 2 + j);
            src = cbcoef; dsel = 64;
        } else {
            int i = (q - 20) >> 1, j = q & 1;
            n = bz * nC + (ty * 2 + i) * Wb16 + (tx2 * 2 + j);
            src = crcoef; dsel = 64;
        }
        unsigned nB = n + (q < 16 ? 4u : 2u);
        const float4* gA = (const float4*)(src + (size_t)n * 64 + x * 8);
        const float4* gB = (const float4*)(src + (size_t)nB * 64 + x * 8);

        // tile-B prefetch: LDGSTS, no registers held
        unsigned w = (unsigned)(q * 96 + 12 * x);
        unsigned sdst = (unsigned)__cvta_generic_to_shared(&bufB[w]);
        asm volatile("cp.async.cg.shared.global [%0], [%1], 16;\n"
                     :: "r"(sdst), "l"(gB) : "memory");
        asm volatile("cp.async.cg.shared.global [%0], [%1], 16;\n"
                     :: "r"(sdst + 16), "l"(gB + 1) : "memory");

        ra = __ldcs(&gA[0]);
        rb = __ldcs(&gA[1]);
    }
    asm volatile("cp.async.commit_group;\n" ::: "memory");

    // ---- stage constants ----
    if (tid < 128) {
        const float* tab = (tid < 64) ? y_table : c_table;
        int o = tid & 63;
        sD[tid] = tab[o] * alpha[o] * fac * 0.25f;
    } else if (tid < 137) {
        sM[tid - 128] = matrix[tid - 128] * (1.0f / 255.0f);
    } else if (tid < 140) {
        int d = tid - 137;
        float k = 0.0f;
#pragma unroll
        for (int c = 0; c < 3; c++)
            k = fmaf(128.0f + shift[c], matrix[c * 3 + d], k);
        sK[d] = k * (1.0f / 255.0f);
    }
    __syncthreads();   // sD/sM/sK ready

    // scale row, reused for both tiles
    float4 da, db4;
    if (tid < 192) {
        const int db = dsel + x * 8;
        da = *(const float4*)&sD[db];
        db4 = *(const float4*)&sD[db + 4];
    }

    // ---- dequant A + pass1 A ----
    if (tid < 192) {
        float a0 = ra.x * da.x, a1 = ra.y * da.y, a2 = ra.z * da.z, a3 = ra.w * da.w;
        float a4 = rb.x * db4.x, a5 = rb.y * db4.y, a6 = rb.z * db4.z, a7 = rb.w * db4.w;
        float* d = &sT[q * 72 + x * 9];
#pragma unroll
        for (int v = 0; v < 8; v++) {
            float acc = a0 * CM[0][v];
            acc = fmaf(a1, CM[1][v], acc);
            acc = fmaf(a2, CM[2][v], acc);
            acc = fmaf(a3, CM[3][v], acc);
            acc = fmaf(a4, CM[4][v], acc);
            acc = fmaf(a5, CM[5][v], acc);
            acc = fmaf(a6, CM[6][v], acc);
            acc = fmaf(a7, CM[7][v], acc);
            d[v] = acc;
        }
    }
    __syncthreads();

    // ---- pass 2 A ----
    if (tid < 192) {
        const int v = x;
        float c0 = sT[q * 72 + 0 * 9 + v];
        float c1 = sT[q * 72 + 1 * 9 + v];
        float c2 = sT[q * 72 + 2 * 9 + v];
        float c3 = sT[q * 72 + 3 * 9 + v];
        float c4 = sT[q * 72 + 4 * 9 + v];
        float c5 = sT[q * 72 + 5 * 9 + v];
        float c6 = sT[q * 72 + 6 * 9 + v];
        float c7 = sT[q * 72 + 7 * 9 + v];

        float* dst; int stride;
        if (q < 16) { dst = &sPY[((q >> 2) * 8) * 32 + (q & 3) * 8 + v]; stride = 32; }
        else if (q < 20) { int b = q - 16; dst = &sPCb[((b >> 1) * 8) * 18 + (b & 1) * 8 + v]; stride = 18; }
        else { int b = q - 20; dst = &sPCr[((b >> 1) * 8) * 18 + (b & 1) * 8 + v]; stride = 18; }

#pragma unroll
        for (int u = 0; u < 8; u++) {
            float acc = c0 * CM[0][u];
            acc = fmaf(c1, CM[1][u], acc);
            acc = fmaf(c2, CM[2][u], acc);
            acc = fmaf(c3, CM[3][u], acc);
            acc = fmaf(c4, CM[4][u], acc);
            acc = fmaf(c5, CM[5][u], acc);
            acc = fmaf(c6, CM[6][u], acc);
            acc = fmaf(c7, CM[7][u], acc);
            dst[u * stride] = acc;
        }
    }
    __syncthreads();

    const float M0 = sM[0], M1 = sM[1], M2 = sM[2];
    const float M3 = sM[3], M4 = sM[4], M5 = sM[5];
    const float M6 = sM[6], M7 = sM[7], M8 = sM[8];
    const float K0 = sK[0], K1 = sK[1], K2 = sK[2];
    const int py = tid >> 3;
    const int px0 = (tid & 7) * 4;
    const int cy = py >> 1, cxb = px0 >> 1;
    const unsigned HW = HH * WW;
    const unsigned base = bz * 3u * HW;
    const unsigned gy = ty * 32 + py;

    // ---- epilogue A (reads sP) + dequant/pass1 B (writes sT) — same phase ----
    {
        float2 cbv = *(const float2*)&sPCb[cy * 18 + cxb];
        float2 crv = *(const float2*)&sPCr[cy * 18 + cxb];
        float4 yv = *(const float4*)&sPY[py * 32 + px0];

        float bR0 = fmaf(cbv.x, M3, fmaf(crv.x, M6, K0));
        float bG0 = fmaf(cbv.x, M4, fmaf(crv.x, M7, K1));
        float bB0 = fmaf(cbv.x, M5, fmaf(crv.x, M8, K2));
        float bR1 = fmaf(cbv.y, M3, fmaf(crv.y, M6, K0));
        float bG1 = fmaf(cbv.y, M4, fmaf(crv.y, M7, K1));
        float bB1 = fmaf(cbv.y, M5, fmaf(crv.y, M8, K2));

        float4 oR, oG, oB;
        oR.x = __saturatef(fmaf(yv.x, M0, bR0));
        oG.x = __saturatef(fmaf(yv.x, M1, bG0));
        oB.x = __saturatef(fmaf(yv.x, M2, bB0));
        oR.y = __saturatef(fmaf(yv.y, M0, bR0));
        oG.y = __saturatef(fmaf(yv.y, M1, bG0));
        oB.y = __saturatef(fmaf(yv.y, M2, bB0));
        oR.z = __saturatef(fmaf(yv.z, M0, bR1));
        oG.z = __saturatef(fmaf(yv.z, M1, bG1));
        oB.z = __saturatef(fmaf(yv.z, M2, bB1));
        oR.w = __saturatef(fmaf(yv.w, M0, bR1));
        oG.w = __saturatef(fmaf(yv.w, M1, bG1));
        oB.w = __saturatef(fmaf(yv.w, M2, bB1));

        const unsigned gx = (tx * 2) * 32 + px0;
        const unsigned off = gy * WW + gx;
        __stcs((float4*)(out + base + off), oR);
        __stcs((float4*)(out + base + HW + off), oG);
        __stcs((float4*)(out + base + 2u * HW + off), oB);
    }

    if (tid < 192) {
        // wait for this thread's cp.async copies, then consume its own row
        asm volatile("cp.async.wait_group 0;\n" ::: "memory");
        const float4* bp = (const float4*)&bufB[q * 96 + 12 * x];
        float4 ra2 = bp[0];
        float4 rb2 = bp[1];

        float a0 = ra2.x * da.x, a1 = ra2.y * da.y, a2 = ra2.z * da.z, a3 = ra2.w * da.w;
        float a4 = rb2.x * db4.x, a5 = rb2.y * db4.y, a6 = rb2.z * db4.z, a7 = rb2.w * db4.w;
        float* d = &sT[q * 72 + x * 9];
#pragma unroll
        for (int v = 0; v < 8; v++) {
            float acc = a0 * CM[0][v];
            acc = fmaf(a1, CM[1][v], acc);
            acc = fmaf(a2, CM[2][v], acc);
            acc = fmaf(a3, CM[3][v], acc);
            acc = fmaf(a4, CM[4][v], acc);
            acc = fmaf(a5, CM[5][v], acc);
            acc = fmaf(a6, CM[6][v], acc);
            acc = fmaf(a7, CM[7][v], acc);
            d[v] = acc;
        }
    }
    __syncthreads();

    // ---- pass 2 B ----
    if (tid < 192) {
        const int v = x;
        float c0 = sT[q * 72 + 0 * 9 + v];
        float c1 = sT[q * 72 + 1 * 9 + v];
        float c2 = sT[q * 72 + 2 * 9 + v];
        float c3 = sT[q * 72 + 3 * 9 + v];
        float c4 = sT[q * 72 + 4 * 9 + v];
        float c5 = sT[q * 72 + 5 * 9 + v];
        float c6 = sT[q * 72 + 6 * 9 + v];
        float c7 = sT[q * 72 + 7 * 9 + v];

        float* dst; int stride;
        if (q < 16) { dst = &sPY[((q >> 2) * 8) * 32 + (q & 3) * 8 + v]; stride = 32; }
        else if (q < 20) { int b = q - 16; dst = &sPCb[((b >> 1) * 8) * 18 + (b & 1) * 8 + v]; stride = 18; }
        else { int b = q - 20; dst = &sPCr[((b >> 1) * 8) * 18 + (b & 1) * 8 + v]; stride = 18; }

#pragma unroll
        for (int u = 0; u < 8; u++) {
            float acc = c0 * CM[0][u];
            acc = fmaf(c1, CM[1][u], acc);
            acc = fmaf(c2, CM[2][u], acc);
            acc = fmaf(c3, CM[3][u], acc);
            acc = fmaf(c4, CM[4][u], acc);
            acc = fmaf(c5, CM[5][u], acc);
            acc = fmaf(c6, CM[6][u], acc);
            acc = fmaf(c7, CM[7][u], acc);
            dst[u * stride] = acc;
        }
    }
    __syncthreads();

    // ---- epilogue B ----
    {
        float2 cbv = *(const float2*)&sPCb[cy * 18 + cxb];
        float2 crv = *(const float2*)&sPCr[cy * 18 + cxb];
        float4 yv = *(const float4*)&sPY[py * 32 + px0];

        float bR0 = fmaf(cbv.x, M3, fmaf(crv.x, M6, K0));
        float bG0 = fmaf(cbv.x, M4, fmaf(crv.x, M7, K1));
        float bB0 = fmaf(cbv.x, M5, fmaf(crv.x, M8, K2));
        float bR1 = fmaf(cbv.y, M3, fmaf(crv.y, M6, K0));
        float bG1 = fmaf(cbv.y, M4, fmaf(crv.y, M7, K1));
        float bB1 = fmaf(cbv.y, M5, fmaf(crv.y, M8, K2));

        float4 oR, oG, oB;
        oR.x = __saturatef(fmaf(yv.x, M0, bR0));
        oG.x = __saturatef(fmaf(yv.x, M1, bG0));
        oB.x = __saturatef(fmaf(yv.x, M2, bB0));
        oR.y = __saturatef(fmaf(yv.y, M0, bR0));
        oG.y = __saturatef(fmaf(yv.y, M1, bG0));
        oB.y = __saturatef(fmaf(yv.y, M2, bB0));
        oR.z = __saturatef(fmaf(yv.z, M0, bR1));
        oG.z = __saturatef(fmaf(yv.z, M1, bG1));
        oB.z = __saturatef(fmaf(yv.z, M2, bB1));
        oR.w = __saturatef(fmaf(yv.w, M0, bR1));
        oG.w = __saturatef(fmaf(yv.w, M1, bG1));
        oB.w = __saturatef(fmaf(yv.w, M2, bB1));

        const unsigned gx = (tx * 2 + 1) * 32 + px0;
        const unsigned off = gy * WW + gx;
        __stcs((float4*)(out + base + off), oR);
        __stcs((float4*)(out + base + HW + off), oG);
        __stcs((float4*)(out + base + 2u * HW + off), oB);
    }
}

extern "C" void kernel_launch(void* const* d_in, const int* in_sizes, int n_in,
                              void* d_out, int out_size) {
    const float* y      = (const float*)d_in[0];
    const float* cb     = (const float*)d_in[1];
    const float* cr     = (const float*)d_in[2];
    const float* ytab   = (const float*)d_in[3];
    const float* ctab   = (const float*)d_in[4];
    const float* alpha  = (const float*)d_in[5];
    const float* shift  = (const float*)d_in[7];
    const float* matrix = (const float*)d_in[8];
    const int* factor   = (const int*)d_in[11];

    int B = in_sizes[0] / (2048 * 2048);
    if (B < 1) B = 1;

    dim3 grid(WW / 64, HH / 32, B);
    jpeg_decode_kernel<<<grid, 256>>>(y, cb, cr, ytab, ctab, alpha, shift,
                                      matrix, factor, (float*)d_out);
}

// round 16
// speedup vs baseline: 1.0644x; 1.0044x over previous
#include <cuda_runtime.h>
#include <cuda_bf16.h>

#define HH 2048
#define WW 2048

__device__ constexpr float CM[8][8] = {
  { 1.0f,         1.0f,         1.0f,         1.0f,         1.0f,         1.0f,         1.0f,         1.0f        },
  { 0.98078528f,  0.83146961f,  0.55557023f,  0.19509032f, -0.19509032f, -0.55557023f, -0.83146961f, -0.98078528f },
  { 0.92387953f,  0.38268343f, -0.38268343f, -0.92387953f, -0.92387953f, -0.38268343f,  0.38268343f,  0.92387953f },
  { 0.83146961f, -0.19509032f, -0.98078528f, -0.55557023f,  0.55557023f,  0.98078528f,  0.19509032f, -0.83146961f },
  { 0.70710678f, -0.70710678f, -0.70710678f,  0.70710678f,  0.70710678f, -0.70710678f, -0.70710678f,  0.70710678f },
  { 0.55557023f, -0.98078528f,  0.19509032f,  0.83146961f, -0.83146961f, -0.19509032f,  0.98078528f, -0.55557023f },
  { 0.38268343f, -0.92387953f,  0.92387953f, -0.38268343f, -0.38268343f,  0.92387953f, -0.92387953f,  0.38268343f },
  { 0.19509032f, -0.55557023f,  0.83146961f, -0.98078528f,  0.98078528f, -0.83146961f,  0.55557023f, -0.19509032f },
};

// One CTA = TWO adjacent 32x32 RGB tiles, cp.async-pipelined (R15 structure).
// R16: __launch_bounds__(256, 6) caps registers at 42 to lift occupancy from
// 5 to 6 CTAs/SM; the dequant scale rows (da/db4) are RELOADED from sD before
// tile-B dequant instead of being held live across the A phases.
__global__ __launch_bounds__(256, 6) void jpeg_decode_kernel(
    const float* __restrict__ ycoef, const float* __restrict__ cbcoef,
    const float* __restrict__ crcoef,
    const float* __restrict__ y_table, const float* __restrict__ c_table,
    const float* __restrict__ alpha, const float* __restrict__ shift,
    const float* __restrict__ matrix, const int* __restrict__ factor_i,
    float* __restrict__ out)
{
    __shared__ float sD[128];
    __shared__ float sM[9];
    __shared__ float sK[3];
    __shared__ float sT[1728];                    // 24 * 72 (reused A/B)
    __shared__ float sPY[32 * 32];                // (reused A/B)
    __shared__ float sPCb[16 * 18];
    __shared__ float sPCr[16 * 18];
    __shared__ __align__(16) float bufB[24 * 96]; // tile-B coeff staging

    const int tid = threadIdx.x;
    const unsigned tx = blockIdx.x, ty = blockIdx.y, bz = blockIdx.z;
    const unsigned Wb8 = WW / 8, Wb16 = WW / 16;
    const unsigned nY = (HH / 8) * (WW / 8);
    const unsigned nC = (HH / 16) * (WW / 16);

    int fbits = factor_i[0];
    float fac = (fbits > 0 && fbits < (1 << 23)) ? (float)fbits
                                                 : __int_as_float(fbits);

    const int q = tid >> 3;
    const int x = tid & 7;

    // ---- issue tile-A LDG (regs) and tile-B cp.async (smem) first ----
    float4 ra, rb;
    int dsel = 0;
    if (tid < 192) {
        const float* src;
        unsigned n;
        unsigned tx2 = tx * 2;
        if (q < 16) {
            int i = q >> 2, j = q & 3;
            n = bz * nY + (ty * 4 + i) * Wb8 + (tx2 * 4 + j);
            src = ycoef;
        } else if (q < 20) {
            int i = (q - 16) >> 1, j = q & 1;
            n = bz * nC + (ty * 2 + i) * Wb16 + (tx2 * 2 + j);
            src = cbcoef; dsel = 64;
        } else {
            int i = (q - 20) >> 1, j = q & 1;
            n = bz * nC + (ty * 2 + i) * Wb16 + (tx2 * 2 + j);
            src = crcoef; dsel = 64;
        }
        unsigned nB = n + (q < 16 ? 4u : 2u);
        const float4* gA = (const float4*)(src + (size_t)n * 64 + x * 8);
        const float4* gB = (const float4*)(src + (size_t)nB * 64 + x * 8);

        unsigned w = (unsigned)(q * 96 + 12 * x);
        unsigned sdst = (unsigned)__cvta_generic_to_shared(&bufB[w]);
        asm volatile("cp.async.cg.shared.global [%0], [%1], 16;\n"
                     :: "r"(sdst), "l"(gB) : "memory");
        asm volatile("cp.async.cg.shared.global [%0], [%1], 16;\n"
                     :: "r"(sdst + 16), "l"(gB + 1) : "memory");

        ra = __ldcs(&gA[0]);
        rb = __ldcs(&gA[1]);
    }
    asm volatile("cp.async.commit_group;\n" ::: "memory");

    // ---- stage constants ----
    if (tid < 128) {
        const float* tab = (tid < 64) ? y_table : c_table;
        int o = tid & 63;
        sD[tid] = tab[o] * alpha[o] * fac * 0.25f;
    } else if (tid < 137) {
        sM[tid - 128] = matrix[tid - 128] * (1.0f / 255.0f);
    } else if (tid < 140) {
        int d = tid - 137;
        float k = 0.0f;
#pragma unroll
        for (int c = 0; c < 3; c++)
            k = fmaf(128.0f + shift[c], matrix[c * 3 + d], k);
        sK[d] = k * (1.0f / 255.0f);
    }
    __syncthreads();   // sD/sM/sK ready

    const int db = dsel + x * 8;

    // ---- dequant A + pass1 A ----
    if (tid < 192) {
        float4 da = *(const float4*)&sD[db];
        float4 db4 = *(const float4*)&sD[db + 4];
        float a0 = ra.x * da.x, a1 = ra.y * da.y, a2 = ra.z * da.z, a3 = ra.w * da.w;
        float a4 = rb.x * db4.x, a5 = rb.y * db4.y, a6 = rb.z * db4.z, a7 = rb.w * db4.w;
        float* d = &sT[q * 72 + x * 9];
#pragma unroll
        for (int v = 0; v < 8; v++) {
            float acc = a0 * CM[0][v];
            acc = fmaf(a1, CM[1][v], acc);
            acc = fmaf(a2, CM[2][v], acc);
            acc = fmaf(a3, CM[3][v], acc);
            acc = fmaf(a4, CM[4][v], acc);
            acc = fmaf(a5, CM[5][v], acc);
            acc = fmaf(a6, CM[6][v], acc);
            acc = fmaf(a7, CM[7][v], acc);
            d[v] = acc;
        }
    }
    __syncthreads();

    // ---- pass 2 A ----
    if (tid < 192) {
        const int v = x;
        float c0 = sT[q * 72 + 0 * 9 + v];
        float c1 = sT[q * 72 + 1 * 9 + v];
        float c2 = sT[q * 72 + 2 * 9 + v];
        float c3 = sT[q * 72 + 3 * 9 + v];
        float c4 = sT[q * 72 + 4 * 9 + v];
        float c5 = sT[q * 72 + 5 * 9 + v];
        float c6 = sT[q * 72 + 6 * 9 + v];
        float c7 = sT[q * 72 + 7 * 9 + v];

        float* dst; int stride;
        if (q < 16) { dst = &sPY[((q >> 2) * 8) * 32 + (q & 3) * 8 + v]; stride = 32; }
        else if (q < 20) { int b = q - 16; dst = &sPCb[((b >> 1) * 8) * 18 + (b & 1) * 8 + v]; stride = 18; }
        else { int b = q - 20; dst = &sPCr[((b >> 1) * 8) * 18 + (b & 1) * 8 + v]; stride = 18; }

#pragma unroll
        for (int u = 0; u < 8; u++) {
            float acc = c0 * CM[0][u];
            acc = fmaf(c1, CM[1][u], acc);
            acc = fmaf(c2, CM[2][u], acc);
            acc = fmaf(c3, CM[3][u], acc);
            acc = fmaf(c4, CM[4][u], acc);
            acc = fmaf(c5, CM[5][u], acc);
            acc = fmaf(c6, CM[6][u], acc);
            acc = fmaf(c7, CM[7][u], acc);
            dst[u * stride] = acc;
        }
    }
    __syncthreads();

    const int py = tid >> 3;
    const int px0 = (tid & 7) * 4;
    const int cy = py >> 1, cxb = px0 >> 1;
    const unsigned HW = HH * WW;
    const unsigned base = bz * 3u * HW;
    const unsigned gy = ty * 32 + py;

    // ---- epilogue A (reads sP) + dequant/pass1 B (writes sT) — same phase ----
    {
        const float M0 = sM[0], M1 = sM[1], M2 = sM[2];
        const float M3 = sM[3], M4 = sM[4], M5 = sM[5];
        const float M6 = sM[6], M7 = sM[7], M8 = sM[8];
        const float K0 = sK[0], K1 = sK[1], K2 = sK[2];

        float2 cbv = *(const float2*)&sPCb[cy * 18 + cxb];
        float2 crv = *(const float2*)&sPCr[cy * 18 + cxb];
        float4 yv = *(const float4*)&sPY[py * 32 + px0];

        float bR0 = fmaf(cbv.x, M3, fmaf(crv.x, M6, K0));
        float bG0 = fmaf(cbv.x, M4, fmaf(crv.x, M7, K1));
        float bB0 = fmaf(cbv.x, M5, fmaf(crv.x, M8, K2));
        float bR1 = fmaf(cbv.y, M3, fmaf(crv.y, M6, K0));
        float bG1 = fmaf(cbv.y, M4, fmaf(crv.y, M7, K1));
        float bB1 = fmaf(cbv.y, M5, fmaf(crv.y, M8, K2));

        float4 oR, oG, oB;
        oR.x = __saturatef(fmaf(yv.x, M0, bR0));
        oG.x = __saturatef(fmaf(yv.x, M1, bG0));
        oB.x = __saturatef(fmaf(yv.x, M2, bB0));
        oR.y = __saturatef(fmaf(yv.y, M0, bR0));
        oG.y = __saturatef(fmaf(yv.y, M1, bG0));
        oB.y = __saturatef(fmaf(yv.y, M2, bB0));
        oR.z = __saturatef(fmaf(yv.z, M0, bR1));
        oG.z = __saturatef(fmaf(yv.z, M1, bG1));
        oB.z = __saturatef(fmaf(yv.z, M2, bB1));
        oR.w = __saturatef(fmaf(yv.w, M0, bR1));
        oG.w = __saturatef(fmaf(yv.w, M1, bG1));
        oB.w = __saturatef(fmaf(yv.w, M2, bB1));

        const unsigned gx = (tx * 2) * 32 + px0;
        const unsigned off = gy * WW + gx;
        __stcs((float4*)(out + base + off), oR);
        __stcs((float4*)(out + base + HW + off), oG);
        __stcs((float4*)(out + base + 2u * HW + off), oB);
    }

    if (tid < 192) {
        // wait for this thread's cp.async copies, then consume its own row;
        // scale rows reloaded from sD (not held across A phases)
        asm volatile("cp.async.wait_group 0;\n" ::: "memory");
        const float4* bp = (const float4*)&bufB[q * 96 + 12 * x];
        float4 ra2 = bp[0];
        float4 rb2 = bp[1];
        float4 da = *(const float4*)&sD[db];
        float4 db4 = *(const float4*)&sD[db + 4];

        float a0 = ra2.x * da.x, a1 = ra2.y * da.y, a2 = ra2.z * da.z, a3 = ra2.w * da.w;
        float a4 = rb2.x * db4.x, a5 = rb2.y * db4.y, a6 = rb2.z * db4.z, a7 = rb2.w * db4.w;
        float* d = &sT[q * 72 + x * 9];
#pragma unroll
        for (int v = 0; v < 8; v++) {
            float acc = a0 * CM[0][v];
            acc = fmaf(a1, CM[1][v], acc);
            acc = fmaf(a2, CM[2][v], acc);
            acc = fmaf(a3, CM[3][v], acc);
            acc = fmaf(a4, CM[4][v], acc);
            acc = fmaf(a5, CM[5][v], acc);
            acc = fmaf(a6, CM[6][v], acc);
            acc = fmaf(a7, CM[7][v], acc);
            d[v] = acc;
        }
    }
    __syncthreads();

    // ---- pass 2 B ----
    if (tid < 192) {
        const int v = x;
        float c0 = sT[q * 72 + 0 * 9 + v];
        float c1 = sT[q * 72 + 1 * 9 + v];
        float c2 = sT[q * 72 + 2 * 9 + v];
        float c3 = sT[q * 72 + 3 * 9 + v];
        float c4 = sT[q * 72 + 4 * 9 + v];
        float c5 = sT[q * 72 + 5 * 9 + v];
        float c6 = sT[q * 72 + 6 * 9 + v];
        float c7 = sT[q * 72 + 7 * 9 + v];

        float* dst; int stride;
        if (q < 16) { dst = &sPY[((q >> 2) * 8) * 32 + (q & 3) * 8 + v]; stride = 32; }
        else if (q < 20) { int b = q - 16; dst = &sPCb[((b >> 1) * 8) * 18 + (b & 1) * 8 + v]; stride = 18; }
        else { int b = q - 20; dst = &sPCr[((b >> 1) * 8) * 18 + (b & 1) * 8 + v]; stride = 18; }

#pragma unroll
        for (int u = 0; u < 8; u++) {
            float acc = c0 * CM[0][u];
            acc = fmaf(c1, CM[1][u], acc);
            acc = fmaf(c2, CM[2][u], acc);
            acc = fmaf(c3, CM[3][u], acc);
            acc = fmaf(c4, CM[4][u], acc);
            acc = fmaf(c5, CM[5][u], acc);
            acc = fmaf(c6, CM[6][u], acc);
            acc = fmaf(c7, CM[7][u], acc);
            dst[u * stride] = acc;
        }
    }
    __syncthreads();

    // ---- epilogue B ----
    {
        const float M0 = sM[0], M1 = sM[1], M2 = sM[2];
        const float M3 = sM[3], M4 = sM[4], M5 = sM[5];
        const float M6 = sM[6], M7 = sM[7], M8 = sM[8];
        const float K0 = sK[0], K1 = sK[1], K2 = sK[2];

        float2 cbv = *(const float2*)&sPCb[cy * 18 + cxb];
        float2 crv = *(const float2*)&sPCr[cy * 18 + cxb];
        float4 yv = *(const float4*)&sPY[py * 32 + px0];

        float bR0 = fmaf(cbv.x, M3, fmaf(crv.x, M6, K0));
        float bG0 = fmaf(cbv.x, M4, fmaf(crv.x, M7, K1));
        float bB0 = fmaf(cbv.x, M5, fmaf(crv.x, M8, K2));
        float bR1 = fmaf(cbv.y, M3, fmaf(crv.y, M6, K0));
        float bG1 = fmaf(cbv.y, M4, fmaf(crv.y, M7, K1));
        float bB1 = fmaf(cbv.y, M5, fmaf(crv.y, M8, K2));

        float4 oR, oG, oB;
        oR.x = __saturatef(fmaf(yv.x, M0, bR0));
        oG.x = __saturatef(fmaf(yv.x, M1, bG0));
        oB.x = __saturatef(fmaf(yv.x, M2, bB0));
        oR.y = __saturatef(fmaf(yv.y, M0, bR0));
        oG.y = __saturatef(fmaf(yv.y, M1, bG0));
        oB.y = __saturatef(fmaf(yv.y, M2, bB0));
        oR.z = __saturatef(fmaf(yv.z, M0, bR1));
        oG.z = __saturatef(fmaf(yv.z, M1, bG1));
        oB.z = __saturatef(fmaf(yv.z, M2, bB1));
        oR.w = __saturatef(fmaf(yv.w, M0, bR1));
        oG.w = __saturatef(fmaf(yv.w, M1, bG1));
        oB.w = __saturatef(fmaf(yv.w, M2, bB1));

        const unsigned gx = (tx * 2 + 1) * 32 + px0;
        const unsigned off = gy * WW + gx;
        __stcs((float4*)(out + base + off), oR);
        __stcs((float4*)(out + base + HW + off), oG);
        __stcs((float4*)(out + base + 2u * HW + off), oB);
    }
}

extern "C" void kernel_launch(void* const* d_in, const int* in_sizes, int n_in,
                              void* d_out, int out_size) {
    const float* y      = (const float*)d_in[0];
    const float* cb     = (const float*)d_in[1];
    const float* cr     = (const float*)d_in[2];
    const float* ytab   = (const float*)d_in[3];
    const float* ctab   = (const float*)d_in[4];
    const float* alpha  = (const float*)d_in[5];
    const float* shift  = (const float*)d_in[7];
    const float* matrix = (const float*)d_in[8];
    const int* factor   = (const int*)d_in[11];

    int B = in_sizes[0] / (2048 * 2048);
    if (B < 1) B = 1;

    dim3 grid(WW / 64, HH / 32, B);
    jpeg_decode_kernel<<<grid, 256>>>(y, cb, cr, ytab, ctab, alpha, shift,
                                      matrix, factor, (float*)d_out);
}